// round 1
// baseline (speedup 1.0000x reference)
#include <cuda_runtime.h>

// Fuzzy min-max composition: out[b,o] = max_i min(m[b,i], clamp(w[i,o], 0, 1))
// B=1024, IN=512, OUT=256 (fp32).
//
// Exact threshold-filter algorithm:
//   1. Per row b, collect indices with m[b,i] > T into a shared list (~64 of 512).
//   2. Each thread scans only the list for its outputs (branch-free, coalesced
//      float2 gathers of w rows; w is L2-resident).
//   3. Completeness proof: if cur >= T then for every unlisted i,
//      min(m[b,i], w) <= m[b,i] <= T <= cur, so the answer is final.
//   4. Otherwise (or on list overflow) fall back to an exact full-row scan.
//      => result is exact for ANY input distribution.

#define IN_DIM  512
#define OUT_DIM 256
#define THREADS 128
#define CAP     192           // mean count ~64, sd ~7.5; 192 is ~17 sigma
#define THRESH  0.875f

__global__ __launch_bounds__(THREADS)
void fuzzy_minmax_kernel(const float* __restrict__ m,
                         const float* __restrict__ w,
                         float* __restrict__ out)
{
    __shared__ float s_m[IN_DIM];     // raw row (for exact fallback)
    __shared__ float s_val[CAP];      // filtered m values
    __shared__ int   s_off[CAP];      // filtered row offsets (i * OUT_DIM)
    __shared__ int   s_cnt;

    const int b = blockIdx.x;
    const int t = threadIdx.x;

    if (t == 0) s_cnt = 0;
    __syncthreads();

    // ---- Phase 1: load row + threshold filter ----
    const float* mrow = m + (size_t)b * IN_DIM;
    #pragma unroll
    for (int i = t; i < IN_DIM; i += THREADS) {
        float v = mrow[i];
        s_m[i] = v;
        if (v > THRESH) {
            int p = atomicAdd(&s_cnt, 1);
            if (p < CAP) { s_val[p] = v; s_off[p] = i * OUT_DIM; }
        }
    }
    __syncthreads();

    int  cnt      = s_cnt;
    bool overflow = (cnt > CAP);
    if (overflow) cnt = 0;            // skip list; everyone takes exact fallback

    // ---- Phase 2: scan filtered list (2 outputs per thread, float2 gathers) ----
    const int o = 2 * t;              // outputs o, o+1
    float c0 = 0.0f, c1 = 0.0f;       // all terms are >= 0, so 0 is a safe identity

    #pragma unroll 4
    for (int k = 0; k < cnt; k++) {
        float ms = s_val[k];
        const float2 wv = *reinterpret_cast<const float2*>(w + s_off[k] + o);
        // lower clamp only: m <= 1 makes min(m, w) == min(m, min(w,1)) for w > 1
        c0 = fmaxf(c0, fminf(ms, fmaxf(wv.x, 0.0f)));
        c1 = fmaxf(c1, fminf(ms, fmaxf(wv.y, 0.0f)));
    }

    // ---- Phase 3: exact fallback when completeness is not proven ----
    if (overflow || c0 < THRESH) {
        float c = 0.0f;
        for (int i = 0; i < IN_DIM; i++)
            c = fmaxf(c, fminf(s_m[i], fmaxf(w[i * OUT_DIM + o], 0.0f)));
        c0 = c;
    }
    if (overflow || c1 < THRESH) {
        float c = 0.0f;
        for (int i = 0; i < IN_DIM; i++)
            c = fmaxf(c, fminf(s_m[i], fmaxf(w[i * OUT_DIM + o + 1], 0.0f)));
        c1 = c;
    }

    float2 r; r.x = c0; r.y = c1;
    *reinterpret_cast<float2*>(out + (size_t)b * OUT_DIM + o) = r;
}

extern "C" void kernel_launch(void* const* d_in, const int* in_sizes, int n_in,
                              void* d_out, int out_size)
{
    const float* m = (const float*)d_in[0];   // [B, IN] fp32
    const float* w = (const float*)d_in[1];   // [IN, OUT] fp32
    float* out = (float*)d_out;               // [B, OUT] fp32

    const int B = in_sizes[0] / IN_DIM;       // 1024 for the reference shapes
    fuzzy_minmax_kernel<<<B, THREADS>>>(m, w, out);
}

// round 3
// speedup vs baseline: 1.0015x; 1.0015x over previous
#include <cuda_runtime.h>

// Fuzzy min-max composition: out[b,o] = max_i min(m[b,i], clamp(w[i,o],0,1))
// B=1024, IN=512, OUT=256, fp32. Exact two-tier threshold filter:
//   tier-1: m > T1 (~32/row), tier-2: T2 < m <= T1 (~32/row), T2=0.875.
//   After tier-1, if every output in the warp already >= T1, all unscanned
//   elements have m <= T1 <= cur -> exact, skip tier-2 (warp-uniform vote).
//   After tier-2, if cur >= T2 -> exact. Else (P~1e-5, or list overflow):
//   exact full-row fallback. Correct for ANY input distribution.
//
// All __ballot_sync/__shfl_sync run on warp-uniform paths (the R2 version
// deadlocked by shuffling inside a divergent branch).

#define IN_DIM  512
#define OUT_DIM 256
#define THREADS 128
#define CAP     128            // per tier; mean ~32, sd ~5.5 -> 128 is ~17 sigma
#define T1      0.9375f
#define T2      0.875f
#define FULL    0xFFFFFFFFu

__global__ __launch_bounds__(THREADS)
void fuzzy_minmax_kernel(const float* __restrict__ m,
                         const float* __restrict__ w,
                         float* __restrict__ out)
{
    __shared__ float  s_m[IN_DIM];    // raw row, for exact fallback
    __shared__ float2 s_hi[CAP];      // {m value, int-bits offset i*OUT_DIM}
    __shared__ float2 s_lo[CAP];
    __shared__ int    s_cnt_hi, s_cnt_lo;

    const int b    = blockIdx.x;
    const int t    = threadIdx.x;
    const int lane = t & 31;

    if (t == 0) { s_cnt_hi = 0; s_cnt_lo = 0; }
    __syncthreads();

    // ---- Phase 1: vectorized row load + warp-aggregated two-tier compaction ----
    const float4 mv = reinterpret_cast<const float4*>(m + (size_t)b * IN_DIM)[t];
    reinterpret_cast<float4*>(s_m)[t] = mv;

    const float vj[4] = {mv.x, mv.y, mv.z, mv.w};
    const unsigned ltmask = (1u << lane) - 1u;
    #pragma unroll
    for (int j = 0; j < 4; j++) {
        const float v = vj[j];
        const int   i = 4 * t + j;
        const bool ph = (v > T1);
        const bool pl = (v > T2) && !ph;
        const unsigned bh = __ballot_sync(FULL, ph);   // all lanes participate
        const unsigned bl = __ballot_sync(FULL, pl);
        if (bh) {                                      // warp-uniform condition
            int base = 0;
            if (lane == 0) base = atomicAdd(&s_cnt_hi, __popc(bh));
            base = __shfl_sync(FULL, base, 0);         // executed by ALL lanes
            if (ph) {
                const int p = base + __popc(bh & ltmask);
                if (p < CAP) s_hi[p] = make_float2(v, __int_as_float(i * OUT_DIM));
            }
        }
        if (bl) {
            int base = 0;
            if (lane == 0) base = atomicAdd(&s_cnt_lo, __popc(bl));
            base = __shfl_sync(FULL, base, 0);
            if (pl) {
                const int p = base + __popc(bl & ltmask);
                if (p < CAP) s_lo[p] = make_float2(v, __int_as_float(i * OUT_DIM));
            }
        }
    }
    __syncthreads();

    int cnt_hi = s_cnt_hi, cnt_lo = s_cnt_lo;
    const bool overflow = (cnt_hi > CAP) || (cnt_lo > CAP);
    if (overflow) { cnt_hi = 0; cnt_lo = 0; }   // force exact fallback

    const int o = 2 * t;                        // outputs o, o+1
    const float* wo = w + o;
    float a0 = 0.f, a1 = 0.f, b0 = 0.f, b1 = 0.f;  // 4 independent chains

    // ---- Phase 2a: tier-1 scan ----
    int k = 0;
    #pragma unroll 4
    for (; k + 2 <= cnt_hi; k += 2) {
        const float2 p0 = s_hi[k], p1 = s_hi[k + 1];
        const float2 w0 = *reinterpret_cast<const float2*>(wo + __float_as_int(p0.y));
        const float2 w1 = *reinterpret_cast<const float2*>(wo + __float_as_int(p1.y));
        a0 = fmaxf(a0, fminf(p0.x, fmaxf(w0.x, 0.f)));
        a1 = fmaxf(a1, fminf(p0.x, fmaxf(w0.y, 0.f)));
        b0 = fmaxf(b0, fminf(p1.x, fmaxf(w1.x, 0.f)));
        b1 = fmaxf(b1, fminf(p1.x, fmaxf(w1.y, 0.f)));
    }
    if (k < cnt_hi) {
        const float2 p0 = s_hi[k];
        const float2 w0 = *reinterpret_cast<const float2*>(wo + __float_as_int(p0.y));
        a0 = fmaxf(a0, fminf(p0.x, fmaxf(w0.x, 0.f)));
        a1 = fmaxf(a1, fminf(p0.x, fmaxf(w0.y, 0.f)));
    }
    float c0 = fmaxf(a0, b0), c1 = fmaxf(a1, b1);

    // ---- Phase 2b: tier-2 scan, skipped if the whole warp is provably done ----
    const unsigned done1 = __ballot_sync(FULL, fminf(c0, c1) >= T1);
    if (done1 != FULL) {                        // warp-uniform
        float d0 = 0.f, d1 = 0.f;
        k = 0;
        #pragma unroll 4
        for (; k + 2 <= cnt_lo; k += 2) {
            const float2 p0 = s_lo[k], p1 = s_lo[k + 1];
            const float2 w0 = *reinterpret_cast<const float2*>(wo + __float_as_int(p0.y));
            const float2 w1 = *reinterpret_cast<const float2*>(wo + __float_as_int(p1.y));
            c0 = fmaxf(c0, fminf(p0.x, fmaxf(w0.x, 0.f)));
            c1 = fmaxf(c1, fminf(p0.x, fmaxf(w0.y, 0.f)));
            d0 = fmaxf(d0, fminf(p1.x, fmaxf(w1.x, 0.f)));
            d1 = fmaxf(d1, fminf(p1.x, fmaxf(w1.y, 0.f)));
        }
        if (k < cnt_lo) {
            const float2 p0 = s_lo[k];
            const float2 w0 = *reinterpret_cast<const float2*>(wo + __float_as_int(p0.y));
            c0 = fmaxf(c0, fminf(p0.x, fmaxf(w0.x, 0.f)));
            c1 = fmaxf(c1, fminf(p0.x, fmaxf(w0.y, 0.f)));
        }
        c0 = fmaxf(c0, d0); c1 = fmaxf(c1, d1);
    }

    // ---- Phase 3: exact fallback when completeness is not proven ----
    if (overflow || c0 < T2) {
        float c = 0.f;
        for (int i = 0; i < IN_DIM; i++)
            c = fmaxf(c, fminf(s_m[i], fmaxf(w[i * OUT_DIM + o], 0.f)));
        c0 = c;
    }
    if (overflow || c1 < T2) {
        float c = 0.f;
        for (int i = 0; i < IN_DIM; i++)
            c = fmaxf(c, fminf(s_m[i], fmaxf(w[i * OUT_DIM + o + 1], 0.f)));
        c1 = c;
    }

    float2 r; r.x = c0; r.y = c1;
    *reinterpret_cast<float2*>(out + (size_t)b * OUT_DIM + o) = r;
}

extern "C" void kernel_launch(void* const* d_in, const int* in_sizes, int n_in,
                              void* d_out, int out_size)
{
    const float* m = (const float*)d_in[0];   // [B, IN] fp32
    const float* w = (const float*)d_in[1];   // [IN, OUT] fp32
    float* out = (float*)d_out;               // [B, OUT] fp32

    const int B = in_sizes[0] / IN_DIM;       // 1024 for the reference shapes
    fuzzy_minmax_kernel<<<B, THREADS>>>(m, w, out);
}

// round 4
// speedup vs baseline: 1.4138x; 1.4116x over previous
#include <cuda_runtime.h>

// Fuzzy min-max composition: out[b,o] = max_i min(m[b,i], clamp(w[i,o],0,1))
// B=1024, IN=512, OUT=256, fp32.
//
// Exact three-tier threshold filter. Tiers: m>T1 (~32), T2<m<=T1 (~32),
// T3<m<=T2 (~64). After each tier, a warp-uniform vote: if every output in
// the warp >= tier threshold, all unscanned elements (m <= threshold) cannot
// raise the max -> exact, stop. Final safety net: warp-COOPERATIVE exact
// full-row scan (16 elems/lane + shuffle reduce) for any output still < T3
// or on list overflow. No serial 512-iteration straggler can exist.
// Correct for ANY input distribution.

#define IN_DIM  512
#define OUT_DIM 256
#define THREADS 128
#define CAP1    128
#define CAP2    128
#define CAP3    192
#define T1      0.9375f
#define T2      0.875f
#define T3      0.75f
#define FULL    0xFFFFFFFFu

__global__ __launch_bounds__(THREADS)
void fuzzy_minmax_kernel(const float* __restrict__ m,
                         const float* __restrict__ w,
                         float* __restrict__ out)
{
    __shared__ float  s_m[IN_DIM];     // raw row (cooperative fallback)
    __shared__ float2 s_t1[CAP1];      // {m value, int-bits offset i*OUT_DIM}
    __shared__ float2 s_t2[CAP2];
    __shared__ float2 s_t3[CAP3];
    __shared__ int    s_c1, s_c2, s_c3;

    const int b    = blockIdx.x;
    const int t    = threadIdx.x;
    const int lane = t & 31;

    if (t == 0) { s_c1 = 0; s_c2 = 0; s_c3 = 0; }
    __syncthreads();

    // ---- Phase 1: vectorized row load + warp-aggregated 3-tier compaction ----
    const float4 mv = reinterpret_cast<const float4*>(m + (size_t)b * IN_DIM)[t];
    reinterpret_cast<float4*>(s_m)[t] = mv;

    const float vj[4] = {mv.x, mv.y, mv.z, mv.w};
    const unsigned ltmask = (1u << lane) - 1u;
    #pragma unroll
    for (int j = 0; j < 4; j++) {
        const float v = vj[j];
        const int   i = 4 * t + j;
        const bool p1 = (v > T1);
        const bool p2 = (v > T2) && !p1;
        const bool p3 = (v > T3) && v <= T2;
        const unsigned b1 = __ballot_sync(FULL, p1);   // all lanes participate
        const unsigned b2 = __ballot_sync(FULL, p2);
        const unsigned b3 = __ballot_sync(FULL, p3);
        if (b1) {                                      // warp-uniform
            int base = 0;
            if (lane == 0) base = atomicAdd(&s_c1, __popc(b1));
            base = __shfl_sync(FULL, base, 0);         // all lanes execute
            if (p1) { int p = base + __popc(b1 & ltmask);
                      if (p < CAP1) s_t1[p] = make_float2(v, __int_as_float(i * OUT_DIM)); }
        }
        if (b2) {
            int base = 0;
            if (lane == 0) base = atomicAdd(&s_c2, __popc(b2));
            base = __shfl_sync(FULL, base, 0);
            if (p2) { int p = base + __popc(b2 & ltmask);
                      if (p < CAP2) s_t2[p] = make_float2(v, __int_as_float(i * OUT_DIM)); }
        }
        if (b3) {
            int base = 0;
            if (lane == 0) base = atomicAdd(&s_c3, __popc(b3));
            base = __shfl_sync(FULL, base, 0);
            if (p3) { int p = base + __popc(b3 & ltmask);
                      if (p < CAP3) s_t3[p] = make_float2(v, __int_as_float(i * OUT_DIM)); }
        }
    }
    __syncthreads();

    int c1n = s_c1, c2n = s_c2, c3n = s_c3;
    const bool overflow = (c1n > CAP1) || (c2n > CAP2) || (c3n > CAP3);
    if (overflow) { c1n = 0; c2n = 0; c3n = 0; }  // everything -> cooperative fallback

    const int o = 2 * t;                          // outputs o, o+1
    const float* wo = w + o;
    float c0 = 0.f, c1 = 0.f;

    // scan helper over a shared list (2-way unroll, 4 independent chains)
    auto scan = [&](const float2* lst, int n, float& r0, float& r1) {
        float a0 = r0, a1 = r1, d0 = 0.f, d1 = 0.f;
        int k = 0;
        #pragma unroll 4
        for (; k + 2 <= n; k += 2) {
            const float2 p0 = lst[k], p1 = lst[k + 1];
            const float2 w0 = *reinterpret_cast<const float2*>(wo + __float_as_int(p0.y));
            const float2 w1 = *reinterpret_cast<const float2*>(wo + __float_as_int(p1.y));
            a0 = fmaxf(a0, fminf(p0.x, fmaxf(w0.x, 0.f)));
            a1 = fmaxf(a1, fminf(p0.x, fmaxf(w0.y, 0.f)));
            d0 = fmaxf(d0, fminf(p1.x, fmaxf(w1.x, 0.f)));
            d1 = fmaxf(d1, fminf(p1.x, fmaxf(w1.y, 0.f)));
        }
        if (k < n) {
            const float2 p0 = lst[k];
            const float2 w0 = *reinterpret_cast<const float2*>(wo + __float_as_int(p0.y));
            a0 = fmaxf(a0, fminf(p0.x, fmaxf(w0.x, 0.f)));
            a1 = fmaxf(a1, fminf(p0.x, fmaxf(w0.y, 0.f)));
        }
        r0 = fmaxf(a0, d0); r1 = fmaxf(a1, d1);
    };

    // ---- Phase 2: tiered scans with warp-uniform completeness votes ----
    scan(s_t1, c1n, c0, c1);
    if (__ballot_sync(FULL, fminf(c0, c1) >= T1) != FULL) {
        scan(s_t2, c2n, c0, c1);
        if (__ballot_sync(FULL, fminf(c0, c1) >= T2) != FULL) {
            scan(s_t3, c3n, c0, c1);
        }
    }

    // ---- Phase 3: warp-cooperative exact fallback (P ~ 1e-13 per output,
    //      or list overflow). 16 elems/lane + shuffle reduction. ----
    unsigned need0 = __ballot_sync(FULL, overflow || c0 < T3);
    unsigned need1 = __ballot_sync(FULL, overflow || c1 < T3);
    while (need0 | need1) {                       // warp-uniform loop
        const bool from0 = (need0 != 0);
        unsigned& nd = from0 ? need0 : need1;
        const int L = __ffs(nd) - 1;
        nd &= nd - 1;
        const int ot = __shfl_sync(FULL, from0 ? o : o + 1, L);
        float acc = 0.f;
        #pragma unroll
        for (int r = 0; r < IN_DIM / 32; r++) {
            const int i = lane + 32 * r;
            acc = fmaxf(acc, fminf(s_m[i], fmaxf(w[i * OUT_DIM + ot], 0.f)));
        }
        #pragma unroll
        for (int d = 16; d; d >>= 1)
            acc = fmaxf(acc, __shfl_xor_sync(FULL, acc, d));
        if (lane == L) { if (from0) c0 = acc; else c1 = acc; }
    }

    float2 r; r.x = c0; r.y = c1;
    *reinterpret_cast<float2*>(out + (size_t)b * OUT_DIM + o) = r;
}

extern "C" void kernel_launch(void* const* d_in, const int* in_sizes, int n_in,
                              void* d_out, int out_size)
{
    const float* m = (const float*)d_in[0];   // [B, IN] fp32
    const float* w = (const float*)d_in[1];   // [IN, OUT] fp32
    float* out = (float*)d_out;               // [B, OUT] fp32

    const int B = in_sizes[0] / IN_DIM;       // 1024 for the reference shapes
    fuzzy_minmax_kernel<<<B, THREADS>>>(m, w, out);
}

// round 5
// speedup vs baseline: 1.4168x; 1.0022x over previous
#include <cuda_runtime.h>

// Fuzzy min-max composition: out[b,o] = max_i min(m[b,i], clamp(w[i,o],0,1))
// B=1024, IN=512, OUT=256, fp32.
//
// Exact three-tier threshold filter (T1=0.9375, T2=0.875, T3=0.75).
// Phase 1 uses two-pass ballot-only compaction: no shared atomics, no
// shuffles, one extra barrier. Tier lists are sentinel-padded to a multiple
// of 8 so the scans run fixed-step fully-unrolled bodies.
// After each tier a warp-uniform vote proves completeness (unscanned i have
// m <= tier threshold <= cur). Safety net: warp-cooperative exact full-row
// scan for any output still < T3 or on list overflow.
// Exact for ANY input distribution.

#define IN_DIM  512
#define OUT_DIM 256
#define THREADS 128
#define NW      4
#define CAP     128           // per tier; mean fill 32/32/64
#define T1      0.9375f
#define T2      0.875f
#define T3      0.75f
#define FULL    0xFFFFFFFFu

__global__ __launch_bounds__(THREADS)
void fuzzy_minmax_kernel(const float* __restrict__ m,
                         const float* __restrict__ w,
                         float* __restrict__ out)
{
    __shared__ float  s_m[IN_DIM];          // raw row (cooperative fallback)
    __shared__ float2 s_t1[CAP + 8];        // {m value, int-bits offset i*OUT_DIM}
    __shared__ float2 s_t2[CAP + 8];
    __shared__ float2 s_t3[CAP + 8];
    __shared__ int    s_cnt[3][NW];

    const int b    = blockIdx.x;
    const int t    = threadIdx.x;
    const int lane = t & 31;
    const int wid  = t >> 5;

    // ---- Pass A: vectorized row load + ballot census (no atomics) ----
    const float4 mv = reinterpret_cast<const float4*>(m + (size_t)b * IN_DIM)[t];
    reinterpret_cast<float4*>(s_m)[t] = mv;

    const float v[4] = {mv.x, mv.y, mv.z, mv.w};
    unsigned m1[4], m2[4], m3[4];
    int c1 = 0, c2 = 0, c3 = 0;
    #pragma unroll
    for (int j = 0; j < 4; j++) {
        const unsigned g1 = __ballot_sync(FULL, v[j] > T1);
        const unsigned g2 = __ballot_sync(FULL, v[j] > T2);
        const unsigned g3 = __ballot_sync(FULL, v[j] > T3);
        m1[j] = g1;
        m2[j] = g2 & ~g1;
        m3[j] = g3 & ~g2;
        c1 += __popc(m1[j]); c2 += __popc(m2[j]); c3 += __popc(m3[j]);
    }
    if (lane == 0) { s_cnt[0][wid] = c1; s_cnt[1][wid] = c2; s_cnt[2][wid] = c3; }
    __syncthreads();

    // ---- Pass B: prefix bases from 12 shared ints; place candidates ----
    int base1 = 0, base2 = 0, base3 = 0, tot1 = 0, tot2 = 0, tot3 = 0;
    #pragma unroll
    for (int ww = 0; ww < NW; ww++) {
        const int n1 = s_cnt[0][ww], n2 = s_cnt[1][ww], n3 = s_cnt[2][ww];
        if (ww < wid) { base1 += n1; base2 += n2; base3 += n3; }
        tot1 += n1; tot2 += n2; tot3 += n3;
    }
    const unsigned ltm = (1u << lane) - 1u;
    int o1 = base1, o2 = base2, o3 = base3;
    #pragma unroll
    for (int j = 0; j < 4; j++) {
        const int i = 4 * t + j;
        const float2 cand = make_float2(v[j], __int_as_float(i * OUT_DIM));
        if (v[j] > T1) {
            const int p = o1 + __popc(m1[j] & ltm); if (p < CAP) s_t1[p] = cand;
        } else if (v[j] > T2) {
            const int p = o2 + __popc(m2[j] & ltm); if (p < CAP) s_t2[p] = cand;
        } else if (v[j] > T3) {
            const int p = o3 + __popc(m3[j] & ltm); if (p < CAP) s_t3[p] = cand;
        }
        o1 += __popc(m1[j]); o2 += __popc(m2[j]); o3 += __popc(m3[j]);
    }
    // sentinel padding (val=0 -> exact no-op in the scan)
    const float2 zz = make_float2(0.f, __int_as_float(0));
    if (t < 8       && tot1 <= CAP) s_t1[tot1 + t]        = zz;
    else if (t < 16 && tot2 <= CAP) s_t2[tot2 + (t - 8)]  = zz;
    else if (t < 24 && tot3 <= CAP) s_t3[tot3 + (t - 16)] = zz;
    __syncthreads();

    const bool overflow = (tot1 > CAP) || (tot2 > CAP) || (tot3 > CAP);
    const int  c1p = overflow ? 0 : (tot1 + 7) & ~7;
    const int  c2p = overflow ? 0 : (tot2 + 7) & ~7;
    const int  c3p = overflow ? 0 : (tot3 + 7) & ~7;

    const int o = 2 * t;                    // outputs o, o+1
    const float* wo = w + o;
    float c0 = 0.f, c1r = 0.f;

    // fixed-step scan: 8 candidates per branch, 4 independent chains
    auto scan = [&](const float2* lst, int np, float& r0, float& r1) {
        float a0 = r0, a1 = r1, d0 = 0.f, d1 = 0.f;
        for (int k = 0; k < np; k += 8) {
            #pragma unroll
            for (int u = 0; u < 8; u += 2) {
                const float2 p0 = lst[k + u], p1 = lst[k + u + 1];
                const float2 w0 = *reinterpret_cast<const float2*>(wo + __float_as_int(p0.y));
                const float2 w1 = *reinterpret_cast<const float2*>(wo + __float_as_int(p1.y));
                a0 = fmaxf(a0, fminf(p0.x, fmaxf(w0.x, 0.f)));
                a1 = fmaxf(a1, fminf(p0.x, fmaxf(w0.y, 0.f)));
                d0 = fmaxf(d0, fminf(p1.x, fmaxf(w1.x, 0.f)));
                d1 = fmaxf(d1, fminf(p1.x, fmaxf(w1.y, 0.f)));
            }
        }
        r0 = fmaxf(a0, d0); r1 = fmaxf(a1, d1);
    };

    // ---- tiered scans with warp-uniform completeness votes ----
    scan(s_t1, c1p, c0, c1r);
    if (__ballot_sync(FULL, fminf(c0, c1r) >= T1) != FULL) {
        scan(s_t2, c2p, c0, c1r);
        if (__ballot_sync(FULL, fminf(c0, c1r) >= T2) != FULL) {
            scan(s_t3, c3p, c0, c1r);
        }
    }

    // ---- warp-cooperative exact fallback (P~1e-13/output, or overflow) ----
    unsigned need0 = __ballot_sync(FULL, overflow || c0  < T3);
    unsigned need1 = __ballot_sync(FULL, overflow || c1r < T3);
    while (need0 | need1) {                 // warp-uniform loop
        const bool from0 = (need0 != 0);
        unsigned& nd = from0 ? need0 : need1;
        const int L = __ffs(nd) - 1;
        nd &= nd - 1;
        const int ot = __shfl_sync(FULL, from0 ? o : o + 1, L);
        float acc = 0.f;
        #pragma unroll
        for (int r = 0; r < IN_DIM / 32; r++) {
            const int i = lane + 32 * r;
            acc = fmaxf(acc, fminf(s_m[i], fmaxf(w[i * OUT_DIM + ot], 0.f)));
        }
        #pragma unroll
        for (int d = 16; d; d >>= 1)
            acc = fmaxf(acc, __shfl_xor_sync(FULL, acc, d));
        if (lane == L) { if (from0) c0 = acc; else c1r = acc; }
    }

    float2 r; r.x = c0; r.y = c1r;
    *reinterpret_cast<float2*>(out + (size_t)b * OUT_DIM + o) = r;
}

extern "C" void kernel_launch(void* const* d_in, const int* in_sizes, int n_in,
                              void* d_out, int out_size)
{
    const float* m = (const float*)d_in[0];   // [B, IN] fp32
    const float* w = (const float*)d_in[1];   // [IN, OUT] fp32
    float* out = (float*)d_out;               // [B, OUT] fp32

    const int B = in_sizes[0] / IN_DIM;       // 1024 for the reference shapes
    fuzzy_minmax_kernel<<<B, THREADS>>>(m, w, out);
}